// round 1
// baseline (speedup 1.0000x reference)
#include <cuda_runtime.h>
#include <cuda_bf16.h>
#include <cstdint>

// Problem dims (fixed for this problem instance)
#define M_DIM 1024
#define K_DIM 4096
#define N_DIM 4096
#define QBLK  32

// Scratch: dequantized fp32 operands (device globals — no allocation allowed)
__device__ float g_xdq[(size_t)M_DIM * K_DIM];          // 16 MB
__device__ float g_wdq[(size_t)N_DIM * K_DIM];          // 64 MB

// ---------------------------------------------------------------------------
// NVFP4 palette snap, matching jnp.argmin tie-to-lower (first index) semantics.
// Thresholds are midpoints; <= keeps the lower palette value on exact ties.
// ---------------------------------------------------------------------------
__device__ __forceinline__ float nvfp4_snap(float a) {
    if (a <= 0.25f) return 0.0f;
    if (a <= 0.75f) return 0.5f;
    if (a <= 1.25f) return 1.0f;
    if (a <= 1.75f) return 1.5f;
    if (a <= 2.5f)  return 2.0f;
    if (a <= 3.5f)  return 3.0f;
    if (a <= 5.0f)  return 4.0f;
    return 6.0f;
}

// One warp per 32-element quant block (blocks are contiguous in row-major K).
// Reproduces reference math exactly in fp32:
//   bm = max(max|v|, 1e-12); scaled = (v/bm)*6; p = snap(|scaled|);
//   dq = sign(scaled) * p * (bm/6)
__global__ void quant_dequant_kernel(const float* __restrict__ t,
                                     float* __restrict__ out,
                                     int total_qblocks) {
    int warp = (int)((blockIdx.x * (size_t)blockDim.x + threadIdx.x) >> 5);
    int lane = threadIdx.x & 31;
    if (warp >= total_qblocks) return;

    size_t idx = (size_t)warp * QBLK + lane;
    float v = t[idx];
    float a = fabsf(v);
    #pragma unroll
    for (int o = 16; o > 0; o >>= 1)
        a = fmaxf(a, __shfl_xor_sync(0xffffffffu, a, o));
    float bm = fmaxf(a, 1e-12f);

    float scaled = (v / bm) * 6.0f;
    float p = nvfp4_snap(fabsf(scaled));
    float s = bm * (1.0f / 6.0f) ;
    // match reference order: scale = bm/6 computed as division
    s = bm / 6.0f;
    float dq = copysignf(p * s, scaled);
    out[idx] = dq;
}

// ---------------------------------------------------------------------------
// Tiled SGEMM, C[M,N] = A[M,K] * B[N,K]^T   (both operands K-major, "NT")
// 128x128 block tile, BK=16, 256 threads, 8x8 per-thread register tile.
// ---------------------------------------------------------------------------
#define BM 128
#define BN 128
#define BK 16
#define TM 8
#define TN 8

__global__ __launch_bounds__(256, 2)
void sgemm_nt_kernel(const float* __restrict__ A,
                     const float* __restrict__ B,
                     float* __restrict__ C) {
    __shared__ float As[BK][BM];
    __shared__ float Bs[BK][BN];

    const int tid = threadIdx.x;
    const int tx = tid & 15;        // 0..15  -> N direction
    const int ty = tid >> 4;        // 0..15  -> M direction
    const int bm0 = blockIdx.y * BM;
    const int bn0 = blockIdx.x * BN;

    float acc[TM][TN];
    #pragma unroll
    for (int i = 0; i < TM; i++)
        #pragma unroll
        for (int j = 0; j < TN; j++)
            acc[i][j] = 0.0f;

    for (int k0 = 0; k0 < K_DIM; k0 += BK) {
        // Each tile is 128 rows x 16 cols = 512 float4 per operand.
        // Thread loads float4 #tid and #(tid+256), stores transposed to smem.
        #pragma unroll
        for (int i = 0; i < 2; i++) {
            int f   = tid + i * 256;
            int row = f >> 2;
            int c4  = (f & 3) << 2;
            float4 va = *(const float4*)&A[(size_t)(bm0 + row) * K_DIM + k0 + c4];
            As[c4 + 0][row] = va.x;
            As[c4 + 1][row] = va.y;
            As[c4 + 2][row] = va.z;
            As[c4 + 3][row] = va.w;
            float4 vb = *(const float4*)&B[(size_t)(bn0 + row) * K_DIM + k0 + c4];
            Bs[c4 + 0][row] = vb.x;
            Bs[c4 + 1][row] = vb.y;
            Bs[c4 + 2][row] = vb.z;
            Bs[c4 + 3][row] = vb.w;
        }
        __syncthreads();

        #pragma unroll
        for (int kk = 0; kk < BK; kk++) {
            float a[TM], b[TN];
            #pragma unroll
            for (int i = 0; i < TM; i += 4) {
                float4 v = *(const float4*)&As[kk][ty * TM + i];
                a[i + 0] = v.x; a[i + 1] = v.y; a[i + 2] = v.z; a[i + 3] = v.w;
            }
            #pragma unroll
            for (int j = 0; j < TN; j += 4) {
                float4 v = *(const float4*)&Bs[kk][tx * TN + j];
                b[j + 0] = v.x; b[j + 1] = v.y; b[j + 2] = v.z; b[j + 3] = v.w;
            }
            #pragma unroll
            for (int i = 0; i < TM; i++)
                #pragma unroll
                for (int j = 0; j < TN; j++)
                    acc[i][j] = fmaf(a[i], b[j], acc[i][j]);
        }
        __syncthreads();
    }

    // Write back 8x8 per-thread tile with float4 stores.
    #pragma unroll
    for (int i = 0; i < TM; i++) {
        int row = bm0 + ty * TM + i;
        #pragma unroll
        for (int j = 0; j < TN; j += 4) {
            float4 v = make_float4(acc[i][j + 0], acc[i][j + 1],
                                   acc[i][j + 2], acc[i][j + 3]);
            *(float4*)&C[(size_t)row * N_DIM + bn0 + tx * TN + j] = v;
        }
    }
}

// ---------------------------------------------------------------------------
// kernel_launch: quantize-dequantize x and w, then SGEMM. Graph-capturable:
// only kernel launches + symbol-address queries (host-side, immediate).
// ---------------------------------------------------------------------------
extern "C" void kernel_launch(void* const* d_in, const int* in_sizes, int n_in,
                              void* d_out, int out_size) {
    (void)n_in; (void)in_sizes; (void)out_size;
    const float* x = (const float*)d_in[0];   // [M, K]
    const float* w = (const float*)d_in[1];   // [N, K]
    float* out = (float*)d_out;               // [M, N]

    float* xdq = nullptr;
    float* wdq = nullptr;
    cudaGetSymbolAddress((void**)&xdq, g_xdq);
    cudaGetSymbolAddress((void**)&wdq, g_wdq);

    // Quantize+dequantize: one warp per 32-elem block, 8 warps per CTA.
    const int xblocks = (M_DIM * K_DIM) / QBLK;   // 131072
    const int wblocks = (N_DIM * K_DIM) / QBLK;   // 524288
    quant_dequant_kernel<<<xblocks / 8, 256>>>(x, xdq, xblocks);
    quant_dequant_kernel<<<wblocks / 8, 256>>>(w, wdq, wblocks);

    // SGEMM: grid = (N/128, M/128) = (32, 8)
    dim3 grid(N_DIM / BN, M_DIM / BM);
    sgemm_nt_kernel<<<grid, 256>>>(xdq, wdq, out);
}

// round 3
// speedup vs baseline: 4.9345x; 4.9345x over previous
#include <cuda_runtime.h>
#include <cuda_bf16.h>
#include <cstdint>

// Problem dims (fixed)
#define M_DIM 1024
#define K_DIM 4096
#define N_DIM 4096
#define QBLK  32
#define NKB   (K_DIM / QBLK)      // 128 scale blocks along K

// GEMM tiling
#define BM 128
#define BN 128
#define BK 64                     // 64 bf16 = 128B rows (SW128 swizzle)
#define STAGES 4
#define NITER (K_DIM / BK)        // 64
#define THREADS 512

// Stage smem layout: A(16K) | B(16K) | sx(1K) | sw(1K)
#define A_OFF   0
#define B_OFF   16384
#define SX_OFF  32768
#define SW_OFF  33792
#define STAGE_B 34816
#define SMEM_TOTAL (STAGES * STAGE_B)   // 139264

// Scratch (device globals — no allocation allowed)
__device__ __nv_bfloat16 g_qx[(size_t)M_DIM * K_DIM];   // 8 MB
__device__ __nv_bfloat16 g_qw[(size_t)N_DIM * K_DIM];   // 32 MB
__device__ float g_sx[(size_t)NKB * M_DIM];             // [kb][m] transposed
__device__ float g_sw[(size_t)NKB * N_DIM];             // [kb][n] transposed

// ---------------------------------------------------------------------------
// PTX helpers (baseline ISA only: cp.async, ldmatrix, mma.sync — sm_80+)
// ---------------------------------------------------------------------------
__device__ __forceinline__ uint32_t smem_u32(const void* p) {
    uint32_t a;
    asm("{ .reg .u64 t; cvta.to.shared.u64 t, %1; cvt.u32.u64 %0, t; }"
        : "=r"(a) : "l"(p));
    return a;
}
#define CP_ASYNC16(dst, src) \
    asm volatile("cp.async.cg.shared.global [%0], [%1], 16;" \
                 :: "r"(dst), "l"(src) : "memory")
#define CP_COMMIT() asm volatile("cp.async.commit_group;" ::: "memory")
#define CP_WAIT(n)  asm volatile("cp.async.wait_group %0;" :: "n"(n) : "memory")

#define LDSM4(r0, r1, r2, r3, addr) \
    asm volatile("ldmatrix.sync.aligned.m8n8.x4.shared.b16 {%0,%1,%2,%3}, [%4];" \
                 : "=r"(r0), "=r"(r1), "=r"(r2), "=r"(r3) : "r"(addr))

// D = A*B + C  (bf16 inputs, f32 accum), m16n8k16 row.col
#define MMA_ACC(d, a, b0, b1) \
    asm volatile("mma.sync.aligned.m16n8k16.row.col.f32.bf16.bf16.f32 " \
        "{%0,%1,%2,%3},{%4,%5,%6,%7},{%8,%9},{%0,%1,%2,%3};" \
        : "+f"((d)[0]), "+f"((d)[1]), "+f"((d)[2]), "+f"((d)[3]) \
        : "r"((a)[0]), "r"((a)[1]), "r"((a)[2]), "r"((a)[3]), "r"(b0), "r"(b1))
#define MMA_ZERO(d, a, b0, b1) \
    asm volatile("mma.sync.aligned.m16n8k16.row.col.f32.bf16.bf16.f32 " \
        "{%0,%1,%2,%3},{%4,%5,%6,%7},{%8,%9},{%10,%10,%10,%10};" \
        : "=f"((d)[0]), "=f"((d)[1]), "=f"((d)[2]), "=f"((d)[3]) \
        : "r"((a)[0]), "r"((a)[1]), "r"((a)[2]), "r"((a)[3]), "r"(b0), "r"(b1), \
          "f"(0.0f))

__device__ __forceinline__ uint32_t swz128(uint32_t off) {
    return off ^ ((off >> 3) & 0x70);
}

// ---------------------------------------------------------------------------
// Quantize kernel v2: each thread handles 4 consecutive elements (float4),
// a 32-elem quant block = 8 threads. Outputs palette values q (bf16, exact)
// and transposed scales s[kb][row] = block_max/6 (fp32).
// ---------------------------------------------------------------------------
__device__ __forceinline__ float nvfp4_snap(float a) {
    if (a <= 0.25f) return 0.0f;
    if (a <= 0.75f) return 0.5f;
    if (a <= 1.25f) return 1.0f;
    if (a <= 1.75f) return 1.5f;
    if (a <= 2.5f)  return 2.0f;
    if (a <= 3.5f)  return 3.0f;
    if (a <= 5.0f)  return 4.0f;
    return 6.0f;
}

__global__ void quant_kernel(const float* __restrict__ t,
                             __nv_bfloat16* __restrict__ q,
                             float* __restrict__ s,
                             int rows) {
    const int gt = blockIdx.x * 256 + threadIdx.x;      // global thread
    const size_t e0 = (size_t)gt * 4;
    if (e0 >= (size_t)rows * K_DIM) return;
    const int lane = threadIdx.x & 31;

    float4 v = *(const float4*)(t + e0);
    float a = fmaxf(fmaxf(fabsf(v.x), fabsf(v.y)),
                    fmaxf(fabsf(v.z), fabsf(v.w)));
    // reduce max over the 8 threads of this 32-elem block
    a = fmaxf(a, __shfl_xor_sync(0xffffffffu, a, 1));
    a = fmaxf(a, __shfl_xor_sync(0xffffffffu, a, 2));
    a = fmaxf(a, __shfl_xor_sync(0xffffffffu, a, 4));
    float bm = fmaxf(a, 1e-12f);

    float inv = 6.0f / bm;   // note: ref does (v/bm)*6; match rounding below
    float q0 = copysignf(nvfp4_snap(fabsf((v.x / bm) * 6.0f)), v.x);
    float q1 = copysignf(nvfp4_snap(fabsf((v.y / bm) * 6.0f)), v.y);
    float q2 = copysignf(nvfp4_snap(fabsf((v.z / bm) * 6.0f)), v.z);
    float q3 = copysignf(nvfp4_snap(fabsf((v.w / bm) * 6.0f)), v.w);
    (void)inv;

    __nv_bfloat162 p01 = __floats2bfloat162_rn(q0, q1);
    __nv_bfloat162 p23 = __floats2bfloat162_rn(q2, q3);
    uint2 pk;
    pk.x = *(uint32_t*)&p01;
    pk.y = *(uint32_t*)&p23;
    *(uint2*)(q + e0) = pk;

    if ((lane & 7) == 0) {
        int row = (int)(e0 / K_DIM);
        int kb  = (int)((e0 % K_DIM) / QBLK);
        s[(size_t)kb * rows + row] = bm / 6.0f;
    }
}

// ---------------------------------------------------------------------------
// Block-scaled bf16 mma.sync GEMM.
// C[m,n] = sum_kb ( sum_{k in kb} qx*qw ) * sx[m,kb] * sw[n,kb]
// CTA 128x128, BK=64 (2 quant blocks / stage), 16 warps of 32x32 tiles.
// ---------------------------------------------------------------------------
__global__ __launch_bounds__(THREADS, 1)
void gemm_qscaled(const __nv_bfloat16* __restrict__ A,  // [M,K] qx
                  const __nv_bfloat16* __restrict__ B,  // [N,K] qw
                  const float* __restrict__ SX,         // [NKB][M]
                  const float* __restrict__ SW,         // [NKB][N]
                  float* __restrict__ C) {
    extern __shared__ __align__(1024) char smem[];
    const uint32_t sb = smem_u32(smem);
    const int tid  = threadIdx.x;
    const int wid  = tid >> 5;
    const int lane = tid & 31;
    const int wm   = wid >> 2;          // 0..3
    const int wn   = wid & 3;           // 0..3
    const int m0   = wm * 32;
    const int n0   = wn * 32;
    const int bm0  = blockIdx.y * BM;
    const int bn0  = blockIdx.x * BN;

    // ---- stage loader (cp.async) ----
    auto load_stage = [&](int buf, int it) {
        const uint32_t st = sb + buf * STAGE_B;
        const int k0 = it * BK;
        #pragma unroll
        for (int i = 0; i < 2; i++) {
            int c = tid + i * THREADS;          // 0..1023
            int row = c >> 3, k16 = c & 7;
            const __nv_bfloat16* gA = A + (size_t)(bm0 + row) * K_DIM + k0 + k16 * 8;
            CP_ASYNC16(st + A_OFF + swz128(row * 128 + k16 * 16), gA);
            const __nv_bfloat16* gB = B + (size_t)(bn0 + row) * K_DIM + k0 + k16 * 8;
            CP_ASYNC16(st + B_OFF + swz128(row * 128 + k16 * 16), gB);
        }
        if (tid < 128) {
            int half = tid >> 6;                // 0 = sx, 1 = sw
            int cc   = tid & 63;
            int kbl  = cc >> 5;                 // quant block within stage
            int qq   = cc & 31;                 // 4-float chunk
            int kb   = it * 2 + kbl;
            if (half == 0) {
                const float* g = SX + (size_t)kb * M_DIM + bm0 + qq * 4;
                CP_ASYNC16(st + SX_OFF + kbl * 512 + qq * 16, g);
            } else {
                const float* g = SW + (size_t)kb * N_DIM + bn0 + qq * 4;
                CP_ASYNC16(st + SW_OFF + kbl * 512 + qq * 16, g);
            }
        }
    };

    float acc[2][4][4];
    #pragma unroll
    for (int i = 0; i < 2; i++)
        #pragma unroll
        for (int j = 0; j < 4; j++)
            #pragma unroll
            for (int e = 0; e < 4; e++)
                acc[i][j][e] = 0.0f;

    // prologue: fill STAGES-1 buffers
    #pragma unroll
    for (int s = 0; s < STAGES - 1; s++) {
        load_stage(s, s);
        CP_COMMIT();
    }

    // precomputed ldmatrix address components (byte offsets within tiles)
    const int aRow = (lane & 15);               // + m0 + tm*16
    const int aColSel = (lane >> 4) * 16;       // byte
    const int bRowLo = (lane & 7) + (((lane >> 4) & 1) << 3);  // + n0 + p*16
    const int bColSel = ((lane >> 3) & 1) * 16;

    for (int it = 0; it < NITER; it++) {
        CP_WAIT(STAGES - 2);
        __syncthreads();

        // prefetch next
        if (it + STAGES - 1 < NITER)
            load_stage((it + STAGES - 1) & (STAGES - 1), it + STAGES - 1);
        CP_COMMIT();

        const int buf = it & (STAGES - 1);
        const uint32_t aB = sb + buf * STAGE_B + A_OFF;
        const uint32_t bB = sb + buf * STAGE_B + B_OFF;
        const char* sxS = smem + buf * STAGE_B + SX_OFF;
        const char* swS = smem + buf * STAGE_B + SW_OFF;

        #pragma unroll
        for (int kb = 0; kb < 2; kb++) {
            float part[2][4][4];
            #pragma unroll
            for (int ks = 0; ks < 2; ks++) {
                const int kbyte = (kb * 2 + ks) * 32;
                uint32_t a[2][4];
                #pragma unroll
                for (int tm = 0; tm < 2; tm++) {
                    uint32_t addr = aB + swz128((m0 + tm * 16 + aRow) * 128 +
                                                kbyte + aColSel);
                    LDSM4(a[tm][0], a[tm][1], a[tm][2], a[tm][3], addr);
                }
                uint32_t b[2][4];
                #pragma unroll
                for (int p = 0; p < 2; p++) {
                    uint32_t addr = bB + swz128((n0 + p * 16 + bRowLo) * 128 +
                                                kbyte + bColSel);
                    LDSM4(b[p][0], b[p][1], b[p][2], b[p][3], addr);
                }
                #pragma unroll
                for (int tm = 0; tm < 2; tm++)
                    #pragma unroll
                    for (int tn = 0; tn < 4; tn++) {
                        uint32_t b0 = b[tn >> 1][(tn & 1) * 2 + 0];
                        uint32_t b1 = b[tn >> 1][(tn & 1) * 2 + 1];
                        if (ks == 0) { MMA_ZERO(part[tm][tn], a[tm], b0, b1); }
                        else         { MMA_ACC (part[tm][tn], a[tm], b0, b1); }
                    }
            }
            // apply block scales: acc += part * (sx*sw)
            float sxv[2][2], swv[4][2];
            #pragma unroll
            for (int tm = 0; tm < 2; tm++)
                #pragma unroll
                for (int h = 0; h < 2; h++)
                    sxv[tm][h] = *(const float*)(sxS + kb * 512 +
                        (m0 + tm * 16 + (lane >> 2) + 8 * h) * 4);
            #pragma unroll
            for (int tn = 0; tn < 4; tn++)
                #pragma unroll
                for (int c = 0; c < 2; c++)
                    swv[tn][c] = *(const float*)(swS + kb * 512 +
                        (n0 + tn * 8 + (lane & 3) * 2 + c) * 4);
            #pragma unroll
            for (int tm = 0; tm < 2; tm++)
                #pragma unroll
                for (int tn = 0; tn < 4; tn++)
                    #pragma unroll
                    for (int e = 0; e < 4; e++)
                        acc[tm][tn][e] = fmaf(part[tm][tn][e],
                                              sxv[tm][e >> 1] * swv[tn][e & 1],
                                              acc[tm][tn][e]);
        }
    }

    // epilogue: write 32x32 warp tile
    #pragma unroll
    for (int tm = 0; tm < 2; tm++)
        #pragma unroll
        for (int h = 0; h < 2; h++) {
            int row = bm0 + m0 + tm * 16 + (lane >> 2) + 8 * h;
            float* cr = C + (size_t)row * N_DIM + bn0 + n0 + (lane & 3) * 2;
            #pragma unroll
            for (int tn = 0; tn < 4; tn++) {
                float2 v = make_float2(acc[tm][tn][h * 2 + 0],
                                       acc[tm][tn][h * 2 + 1]);
                *(float2*)(cr + tn * 8) = v;
            }
        }
}

// ---------------------------------------------------------------------------
extern "C" void kernel_launch(void* const* d_in, const int* in_sizes, int n_in,
                              void* d_out, int out_size) {
    (void)n_in; (void)in_sizes; (void)out_size;
    const float* x = (const float*)d_in[0];   // [M, K]
    const float* w = (const float*)d_in[1];   // [N, K]
    float* out = (float*)d_out;               // [M, N]

    __nv_bfloat16 *qx = nullptr, *qw = nullptr;
    float *sx = nullptr, *sw = nullptr;
    cudaGetSymbolAddress((void**)&qx, g_qx);
    cudaGetSymbolAddress((void**)&qw, g_qw);
    cudaGetSymbolAddress((void**)&sx, g_sx);
    cudaGetSymbolAddress((void**)&sw, g_sw);

    // quant: 4 elems/thread, 256 threads/CTA
    quant_kernel<<<(M_DIM * K_DIM) / 4 / 256, 256>>>(x, qx, sx, M_DIM);
    quant_kernel<<<(N_DIM * K_DIM) / 4 / 256, 256>>>(w, qw, sw, N_DIM);

    cudaFuncSetAttribute(gemm_qscaled,
                         cudaFuncAttributeMaxDynamicSharedMemorySize,
                         SMEM_TOTAL);
    dim3 grid(N_DIM / BN, M_DIM / BM);        // (32, 8)
    gemm_qscaled<<<grid, THREADS, SMEM_TOTAL>>>(qx, qw, sx, sw, out);
}

// round 4
// speedup vs baseline: 5.4040x; 1.0951x over previous
#include <cuda_runtime.h>
#include <cuda_bf16.h>
#include <cstdint>

// Problem dims (fixed)
#define M_DIM 1024
#define K_DIM 4096
#define N_DIM 4096
#define QBLK  32
#define NKB   (K_DIM / QBLK)      // 128

// GEMM tiling (fp8 path)
#define BM 128
#define BN 128
#define BK 128                    // 128 fp8 = 128B rows (SW128), 4 quant blocks
#define STAGES 4
#define NITER (K_DIM / BK)        // 32
#define THREADS 512

// Stage smem: A(16K) | B(16K) | sx(2K) | sw(2K)
#define A_OFF   0
#define B_OFF   16384
#define SX_OFF  32768
#define SW_OFF  34816
#define STAGE_B 36864
#define SMEM_TOTAL (STAGES * STAGE_B)   // 147456

// Scratch (device globals)
__device__ uint8_t g_qx[(size_t)M_DIM * K_DIM];   // 4 MB  (e4m3)
__device__ uint8_t g_qw[(size_t)N_DIM * K_DIM];   // 16 MB (e4m3)
__device__ float   g_sx[(size_t)NKB * M_DIM];     // [kb][m]
__device__ float   g_sw[(size_t)NKB * N_DIM];     // [kb][n]

// ---------------------------------------------------------------------------
// PTX helpers
// ---------------------------------------------------------------------------
__device__ __forceinline__ uint32_t smem_u32(const void* p) {
    uint32_t a;
    asm("{ .reg .u64 t; cvta.to.shared.u64 t, %1; cvt.u32.u64 %0, t; }"
        : "=r"(a) : "l"(p));
    return a;
}
#define CP_ASYNC16(dst, src) \
    asm volatile("cp.async.cg.shared.global [%0], [%1], 16;" \
                 :: "r"(dst), "l"(src) : "memory")
#define CP_COMMIT() asm volatile("cp.async.commit_group;" ::: "memory")
#define CP_WAIT(n)  asm volatile("cp.async.wait_group %0;" :: "n"(n) : "memory")

#define LDSM4(r0, r1, r2, r3, addr) \
    asm volatile("ldmatrix.sync.aligned.m8n8.x4.shared.b16 {%0,%1,%2,%3}, [%4];" \
                 : "=r"(r0), "=r"(r1), "=r"(r2), "=r"(r3) : "r"(addr))

// fp8 e4m3 MMA, K=32, fp32 accum, C = 0 (exact partial over one quant block)
#define MMA_FP8_Z(d, a, b0, b1) \
    asm volatile("mma.sync.aligned.m16n8k32.row.col.f32.e4m3.e4m3.f32 " \
        "{%0,%1,%2,%3},{%4,%5,%6,%7},{%8,%9},{%10,%10,%10,%10};" \
        : "=f"((d)[0]), "=f"((d)[1]), "=f"((d)[2]), "=f"((d)[3]) \
        : "r"((a)[0]), "r"((a)[1]), "r"((a)[2]), "r"((a)[3]), \
          "r"(b0), "r"(b1), "f"(0.0f))

// packed f32x2 ops (sm_100+ family baseline)
__device__ __forceinline__ unsigned long long pk2(float lo, float hi) {
    unsigned long long d;
    asm("mov.b64 %0, {%1, %2};" : "=l"(d) : "f"(lo), "f"(hi));
    return d;
}
__device__ __forceinline__ unsigned long long pmul2(unsigned long long a,
                                                    unsigned long long b) {
    unsigned long long d;
    asm("mul.rn.f32x2 %0, %1, %2;" : "=l"(d) : "l"(a), "l"(b));
    return d;
}
__device__ __forceinline__ void pfma2(unsigned long long& acc,
                                      unsigned long long a,
                                      unsigned long long b) {
    asm("fma.rn.f32x2 %0, %1, %2, %0;" : "+l"(acc) : "l"(a), "l"(b));
}

__device__ __forceinline__ uint32_t swz128(uint32_t off) {
    return off ^ ((off >> 3) & 0x70);
}

// ---------------------------------------------------------------------------
// Quantize: 8 elems/thread, 4 threads per 32-elem block. Outputs e4m3 palette
// bytes (exact) and transposed fp32 scales s[kb][row] = block_max/6.
// ---------------------------------------------------------------------------
__device__ __forceinline__ uint32_t pal_byte(float u, float r6) {
    float su = fabsf(u) * r6;
    uint32_t l = (su > 0.25f) + (su > 0.75f) + (su > 1.25f) + (su > 1.75f) +
                 (su > 2.5f)  + (su > 3.5f)  + (su > 5.0f);
    uint32_t b = __byte_perm(0x3C383000u, 0x4C484440u, l) & 0xffu;
    return b | ((__float_as_uint(u) >> 31) << 7);
}

__global__ void quant_kernel(const float* __restrict__ t,
                             uint8_t* __restrict__ q,
                             float* __restrict__ s,
                             int rows) {
    const size_t gt = blockIdx.x * 256 + threadIdx.x;
    const size_t e0 = gt * 8;
    if (e0 >= (size_t)rows * K_DIM) return;

    float4 v0 = *(const float4*)(t + e0);
    float4 v1 = *(const float4*)(t + e0 + 4);
    float a = fmaxf(fmaxf(fmaxf(fabsf(v0.x), fabsf(v0.y)),
                          fmaxf(fabsf(v0.z), fabsf(v0.w))),
                    fmaxf(fmaxf(fabsf(v1.x), fabsf(v1.y)),
                          fmaxf(fabsf(v1.z), fabsf(v1.w))));
    a = fmaxf(a, __shfl_xor_sync(0xffffffffu, a, 1));
    a = fmaxf(a, __shfl_xor_sync(0xffffffffu, a, 2));
    float bm = fmaxf(a, 1e-12f);
    float r6 = 6.0f / bm;

    uint32_t b0 =  pal_byte(v0.x, r6)        | (pal_byte(v0.y, r6) << 8) |
                  (pal_byte(v0.z, r6) << 16) | (pal_byte(v0.w, r6) << 24);
    uint32_t b1 =  pal_byte(v1.x, r6)        | (pal_byte(v1.y, r6) << 8) |
                  (pal_byte(v1.z, r6) << 16) | (pal_byte(v1.w, r6) << 24);
    *(uint2*)(q + e0) = make_uint2(b0, b1);

    if ((threadIdx.x & 3) == 0) {
        int row = (int)(e0 / K_DIM);
        int kb  = (int)((e0 % K_DIM) / QBLK);
        s[(size_t)kb * rows + row] = bm / 6.0f;
    }
}

// ---------------------------------------------------------------------------
// FP8 block-scaled GEMM: C[m,n] = sum_kb mma_k32(qx,qw) * sx[m,kb]*sw[n,kb]
// CTA 128x128, BK=128 (4 quant blocks/stage), 16 warps of 32x32 tiles.
// ---------------------------------------------------------------------------
__global__ __launch_bounds__(THREADS, 1)
void gemm_fp8(const uint8_t* __restrict__ A,   // [M,K] e4m3
              const uint8_t* __restrict__ B,   // [N,K] e4m3
              const float* __restrict__ SX,    // [NKB][M]
              const float* __restrict__ SW,    // [NKB][N]
              float* __restrict__ C) {
    extern __shared__ __align__(1024) char smem[];
    const uint32_t sb = smem_u32(smem);
    const int tid  = threadIdx.x;
    const int wid  = tid >> 5;
    const int lane = tid & 31;
    const int m0   = (wid >> 2) * 32;
    const int n0   = (wid & 3) * 32;
    const int bm0  = blockIdx.y * BM;
    const int bn0  = blockIdx.x * BN;

    auto load_stage = [&](int buf, int it) {
        const uint32_t st = sb + buf * STAGE_B;
        const int k0 = it * BK;
        #pragma unroll
        for (int i = 0; i < 2; i++) {
            int c = tid + i * THREADS;          // 0..1023
            int row = c >> 3, k16 = c & 7;
            const uint8_t* gA = A + (size_t)(bm0 + row) * K_DIM + k0 + k16 * 16;
            CP_ASYNC16(st + A_OFF + swz128(row * 128 + k16 * 16), gA);
            const uint8_t* gB = B + (size_t)(bn0 + row) * K_DIM + k0 + k16 * 16;
            CP_ASYNC16(st + B_OFF + swz128(row * 128 + k16 * 16), gB);
        }
        if (tid < 256) {
            int half = tid >> 7;                // 0 = sx, 1 = sw
            int cc   = tid & 127;
            int kbl  = cc >> 5;                 // 0..3
            int qq   = cc & 31;
            int kb   = it * 4 + kbl;
            if (half == 0) {
                const float* g = SX + (size_t)kb * M_DIM + bm0 + qq * 4;
                CP_ASYNC16(st + SX_OFF + kbl * 512 + qq * 16, g);
            } else {
                const float* g = SW + (size_t)kb * N_DIM + bn0 + qq * 4;
                CP_ASYNC16(st + SW_OFF + kbl * 512 + qq * 16, g);
            }
        }
    };

    // packed accumulators: acc2[tm][tn][h] = (c_even, c_odd) fp32 pair
    unsigned long long acc2[2][4][2];
    #pragma unroll
    for (int i = 0; i < 2; i++)
        #pragma unroll
        for (int j = 0; j < 4; j++) {
            acc2[i][j][0] = 0ull; acc2[i][j][1] = 0ull;
        }

    #pragma unroll
    for (int s = 0; s < STAGES - 1; s++) {
        load_stage(s, s);
        CP_COMMIT();
    }

    // ldmatrix lane addressing
    const int r       = lane & 7;
    const int sel     = lane >> 3;
    const int selRow  = (sel & 1) * 8;
    const int selByte = (sel >> 1) * 16;
    const int qrow    = lane >> 2;   // 0..7
    const int qcol    = (lane & 3) * 2;

    for (int it = 0; it < NITER; it++) {
        CP_WAIT(STAGES - 2);
        __syncthreads();

        if (it + STAGES - 1 < NITER)
            load_stage((it + STAGES - 1) & (STAGES - 1), it + STAGES - 1);
        CP_COMMIT();

        const int buf = it & (STAGES - 1);
        const uint32_t aB = sb + buf * STAGE_B + A_OFF;
        const uint32_t bB = sb + buf * STAGE_B + B_OFF;
        const char* sxS = smem + buf * STAGE_B + SX_OFF;
        const char* swS = smem + buf * STAGE_B + SW_OFF;

        #pragma unroll
        for (int kb = 0; kb < 4; kb++) {
            const int kbyte = kb * 32 + selByte;
            uint32_t a[2][4];
            #pragma unroll
            for (int tm = 0; tm < 2; tm++) {
                uint32_t addr = aB + swz128((m0 + tm * 16 + r + selRow) * 128 + kbyte);
                LDSM4(a[tm][0], a[tm][1], a[tm][2], a[tm][3], addr);
            }
            uint32_t b[2][4];
            #pragma unroll
            for (int g = 0; g < 2; g++) {
                uint32_t addr = bB + swz128((n0 + g * 16 + r + selRow) * 128 + kbyte);
                LDSM4(b[g][0], b[g][1], b[g][2], b[g][3], addr);
            }

            float part[2][4][4];
            #pragma unroll
            for (int tm = 0; tm < 2; tm++)
                #pragma unroll
                for (int g = 0; g < 2; g++) {
                    MMA_FP8_Z(part[tm][2*g],     a[tm], b[g][0], b[g][2]);
                    MMA_FP8_Z(part[tm][2*g + 1], a[tm], b[g][1], b[g][3]);
                }

            // scales
            unsigned long long sxd[2][2];
            #pragma unroll
            for (int tm = 0; tm < 2; tm++)
                #pragma unroll
                for (int h = 0; h < 2; h++) {
                    float sx = *(const float*)(sxS + kb * 512 +
                                               (m0 + tm * 16 + qrow + 8 * h) * 4);
                    sxd[tm][h] = pk2(sx, sx);
                }
            unsigned long long swp[4];
            #pragma unroll
            for (int tn = 0; tn < 4; tn++)
                swp[tn] = *(const unsigned long long*)(swS + kb * 512 +
                                                       (n0 + tn * 8 + qcol) * 4);
            #pragma unroll
            for (int tm = 0; tm < 2; tm++)
                #pragma unroll
                for (int tn = 0; tn < 4; tn++) {
                    unsigned long long p01 = pk2(part[tm][tn][0], part[tm][tn][1]);
                    unsigned long long p23 = pk2(part[tm][tn][2], part[tm][tn][3]);
                    pfma2(acc2[tm][tn][0], p01, pmul2(sxd[tm][0], swp[tn]));
                    pfma2(acc2[tm][tn][1], p23, pmul2(sxd[tm][1], swp[tn]));
                }
        }
    }

    // epilogue: 8-byte packed stores
    #pragma unroll
    for (int tm = 0; tm < 2; tm++)
        #pragma unroll
        for (int h = 0; h < 2; h++) {
            int row = bm0 + m0 + tm * 16 + qrow + 8 * h;
            #pragma unroll
            for (int tn = 0; tn < 4; tn++) {
                unsigned long long v = acc2[tm][tn][h];
                *(unsigned long long*)(C + (size_t)row * N_DIM +
                                       bn0 + n0 + tn * 8 + qcol) = v;
            }
        }
}

// ---------------------------------------------------------------------------
extern "C" void kernel_launch(void* const* d_in, const int* in_sizes, int n_in,
                              void* d_out, int out_size) {
    (void)n_in; (void)in_sizes; (void)out_size;
    const float* x = (const float*)d_in[0];   // [M, K]
    const float* w = (const float*)d_in[1];   // [N, K]
    float* out = (float*)d_out;               // [M, N]

    uint8_t *qx = nullptr, *qw = nullptr;
    float *sx = nullptr, *sw = nullptr;
    cudaGetSymbolAddress((void**)&qx, g_qx);
    cudaGetSymbolAddress((void**)&qw, g_qw);
    cudaGetSymbolAddress((void**)&sx, g_sx);
    cudaGetSymbolAddress((void**)&sw, g_sw);

    quant_kernel<<<(M_DIM * (size_t)K_DIM) / 8 / 256, 256>>>(x, qx, sx, M_DIM);
    quant_kernel<<<(N_DIM * (size_t)K_DIM) / 8 / 256, 256>>>(w, qw, sw, N_DIM);

    cudaFuncSetAttribute(gemm_fp8,
                         cudaFuncAttributeMaxDynamicSharedMemorySize,
                         SMEM_TOTAL);
    dim3 grid(N_DIM / BN, M_DIM / BM);        // (32, 8)
    gemm_fp8<<<grid, THREADS, SMEM_TOTAL>>>(qx, qw, sx, sw, out);
}